// round 2
// baseline (speedup 1.0000x reference)
#include <cuda_runtime.h>
#include <cuda_bf16.h>

// Problem constants
static constexpr int Nn = 200000;   // nodes
static constexpr int Ee = 400000;   // edges
static constexpr int Gg = 4096;     // graphs
static constexpr int USR = 12;

// Scratch (device globals; no allocation allowed)
__device__ float g_agg[(size_t)Nn * 64];        // 51.2 MB
__device__ float g_h[(size_t)Nn * 64];          // 51.2 MB (layer1 output)
__device__ float g_pool[(size_t)Gg * 129];      // pool sums [G,128] + counts [G]

// ---------------------------------------------------------------------------
// zero fill
__global__ void zero_kernel(float4* __restrict__ p, int n4) {
    int i = blockIdx.x * blockDim.x + threadIdx.x;
    if (i < n4) p[i] = make_float4(0.f, 0.f, 0.f, 0.f);
}

// ---------------------------------------------------------------------------
// Edge message + scatter:  agg[dst] += relu(x[src] + ea @ EW + eb)
// 16 edges per 256-thread block; 16 threads per edge; 4 channels per thread.
__global__ __launch_bounds__(256) void edge_kernel(
    const float* __restrict__ xin, const int* __restrict__ ei,
    const float* __restrict__ ea, const float* __restrict__ ew,
    const float* __restrict__ eb, float* __restrict__ agg)
{
    __shared__ float sW[16 * 64];
    __shared__ float sEA[16 * 16];
    __shared__ int sS[16], sD[16];

    int tid = threadIdx.x;
    int e0 = blockIdx.x * 16;

    for (int i = tid; i < 16 * 64; i += 256) sW[i] = ew[i];
    {
        int e = e0 + (tid >> 4);
        if (e < Ee) sEA[tid] = ea[(size_t)e * 16 + (tid & 15)];
    }
    if (tid < 16) {
        int e = e0 + tid;
        if (e < Ee) { sS[tid] = ei[e]; sD[tid] = ei[Ee + e]; }
    }
    __syncthreads();

    int le = tid >> 4, q = tid & 15;
    int e = e0 + le;
    if (e >= Ee) return;

    const float* eaL = &sEA[le * 16];
    float4 acc = ((const float4*)eb)[q];
#pragma unroll
    for (int k = 0; k < 16; ++k) {
        float a = eaL[k];
        float4 w = ((const float4*)(sW + k * 64))[q];
        acc.x = fmaf(a, w.x, acc.x);
        acc.y = fmaf(a, w.y, acc.y);
        acc.z = fmaf(a, w.z, acc.z);
        acc.w = fmaf(a, w.w, acc.w);
    }
    size_t s = (size_t)sS[le], d = (size_t)sD[le];
    float4 xv = ((const float4*)(xin + s * 64))[q];
    acc.x = fmaxf(acc.x + xv.x, 0.f);
    acc.y = fmaxf(acc.y + xv.y, 0.f);
    acc.z = fmaxf(acc.z + xv.z, 0.f);
    acc.w = fmaxf(acc.w + xv.w, 0.f);

    float* p = agg + d * 64 + q * 4;
    asm volatile("red.global.add.v4.f32 [%0], {%1,%2,%3,%4};"
                 :: "l"(p), "f"(acc.x), "f"(acc.y), "f"(acc.z), "f"(acc.w)
                 : "memory");
}

// ---------------------------------------------------------------------------
// Node MLP layer 1: hout = relu( relu((x+agg)@W1 + b1) @ W2 + b2 )   (64->64->64)
// 64 rows per 256-thread block. Thread tile 4 rows x 4 cols.
__global__ __launch_bounds__(256) void node1_kernel(
    const float* __restrict__ xin, const float* __restrict__ agg,
    const float* __restrict__ W1, const float* __restrict__ b1,
    const float* __restrict__ W2, const float* __restrict__ b2,
    float* __restrict__ hout)
{
    extern __shared__ float sm[];
    float* sH = sm;          // 64*64
    float* sT = sm + 4096;   // 64*64
    float* sW = sm + 8192;   // 64*64 (W1, then W2)

    int tid = threadIdx.x;
    size_t base = (size_t)blockIdx.x * 64 * 64;

    float4* sH4 = (float4*)sH;
    const float4* x4 = (const float4*)(xin + base);
    const float4* a4 = (const float4*)(agg + base);
    for (int i = tid; i < 1024; i += 256) {
        float4 xv = x4[i], av = a4[i];
        xv.x += av.x; xv.y += av.y; xv.z += av.z; xv.w += av.w;
        sH4[i] = xv;
    }
    float4* sW4 = (float4*)sW;
    for (int i = tid; i < 1024; i += 256) sW4[i] = ((const float4*)W1)[i];
    __syncthreads();

    int tx = tid & 15, ty = tid >> 4;
    int c0 = tx * 4, r0 = ty * 4;

    float acc[4][4];
    {
        float4 bb = ((const float4*)b1)[tx];
#pragma unroll
        for (int i = 0; i < 4; ++i) { acc[i][0] = bb.x; acc[i][1] = bb.y; acc[i][2] = bb.z; acc[i][3] = bb.w; }
    }
#pragma unroll 4
    for (int k = 0; k < 64; ++k) {
        float4 w = ((const float4*)(sW + k * 64))[tx];
#pragma unroll
        for (int i = 0; i < 4; ++i) {
            float h = sH[(r0 + i) * 64 + k];
            acc[i][0] = fmaf(h, w.x, acc[i][0]);
            acc[i][1] = fmaf(h, w.y, acc[i][1]);
            acc[i][2] = fmaf(h, w.z, acc[i][2]);
            acc[i][3] = fmaf(h, w.w, acc[i][3]);
        }
    }
#pragma unroll
    for (int i = 0; i < 4; ++i) {
        float4 v = make_float4(fmaxf(acc[i][0], 0.f), fmaxf(acc[i][1], 0.f),
                               fmaxf(acc[i][2], 0.f), fmaxf(acc[i][3], 0.f));
        *(float4*)&sT[(r0 + i) * 64 + c0] = v;
    }
    __syncthreads();
    for (int i = tid; i < 1024; i += 256) sW4[i] = ((const float4*)W2)[i];
    __syncthreads();

    {
        float4 bb = ((const float4*)b2)[tx];
#pragma unroll
        for (int i = 0; i < 4; ++i) { acc[i][0] = bb.x; acc[i][1] = bb.y; acc[i][2] = bb.z; acc[i][3] = bb.w; }
    }
#pragma unroll 4
    for (int k = 0; k < 64; ++k) {
        float4 w = ((const float4*)(sW + k * 64))[tx];
#pragma unroll
        for (int i = 0; i < 4; ++i) {
            float t = sT[(r0 + i) * 64 + k];
            acc[i][0] = fmaf(t, w.x, acc[i][0]);
            acc[i][1] = fmaf(t, w.y, acc[i][1]);
            acc[i][2] = fmaf(t, w.z, acc[i][2]);
            acc[i][3] = fmaf(t, w.w, acc[i][3]);
        }
    }
#pragma unroll
    for (int i = 0; i < 4; ++i) {
        float4 v = make_float4(fmaxf(acc[i][0], 0.f), fmaxf(acc[i][1], 0.f),
                               fmaxf(acc[i][2], 0.f), fmaxf(acc[i][3], 0.f));
        *(float4*)&hout[base + (size_t)(r0 + i) * 64 + c0] = v;
    }
}

// ---------------------------------------------------------------------------
// Node MLP layer 2 + pooling:
// out = relu((h+agg)@W1 + b1) @ W2 + b2     (64 -> 128 -> 128, no outer relu)
// pool[batch[row]] += out[row];  cnt[batch[row]] += 1
// 64 rows per 256-thread block. Thread tile 8 rows x 4 cols (128 cols total).
__global__ __launch_bounds__(256) void node2_kernel(
    const float* __restrict__ hin, const float* __restrict__ agg,
    const float* __restrict__ W1, const float* __restrict__ b1,
    const float* __restrict__ W2, const float* __restrict__ b2,
    const int* __restrict__ batch,
    float* __restrict__ pool, float* __restrict__ cnt)
{
    extern __shared__ float sm[];
    float* sH = sm;             // 64*64   = 4096
    float* sT = sm + 4096;      // 64*128  = 8192
    float* sW = sm + 12288;     // up to 128*128 = 16384
    int*  sB = (int*)(sm + 28672); // 64 ints

    int tid = threadIdx.x;
    int row0 = blockIdx.x * 64;
    size_t base = (size_t)row0 * 64;

    float4* sH4 = (float4*)sH;
    const float4* x4 = (const float4*)(hin + base);
    const float4* a4 = (const float4*)(agg + base);
    for (int i = tid; i < 1024; i += 256) {
        float4 xv = x4[i], av = a4[i];
        xv.x += av.x; xv.y += av.y; xv.z += av.z; xv.w += av.w;
        sH4[i] = xv;
    }
    float4* sW4 = (float4*)sW;
    for (int i = tid; i < 2048; i += 256) sW4[i] = ((const float4*)W1)[i];
    if (tid < 64) sB[tid] = batch[row0 + tid];
    __syncthreads();

    int tx = tid & 31, ty = tid >> 5;
    int c0 = tx * 4, r0 = ty * 8;

    float acc[8][4];
    {
        float4 bb = ((const float4*)b1)[tx];
#pragma unroll
        for (int i = 0; i < 8; ++i) { acc[i][0] = bb.x; acc[i][1] = bb.y; acc[i][2] = bb.z; acc[i][3] = bb.w; }
    }
#pragma unroll 2
    for (int k = 0; k < 64; ++k) {
        float4 w = ((const float4*)(sW + k * 128))[tx];
#pragma unroll
        for (int i = 0; i < 8; ++i) {
            float h = sH[(r0 + i) * 64 + k];
            acc[i][0] = fmaf(h, w.x, acc[i][0]);
            acc[i][1] = fmaf(h, w.y, acc[i][1]);
            acc[i][2] = fmaf(h, w.z, acc[i][2]);
            acc[i][3] = fmaf(h, w.w, acc[i][3]);
        }
    }
#pragma unroll
    for (int i = 0; i < 8; ++i) {
        float4 v = make_float4(fmaxf(acc[i][0], 0.f), fmaxf(acc[i][1], 0.f),
                               fmaxf(acc[i][2], 0.f), fmaxf(acc[i][3], 0.f));
        *(float4*)&sT[(r0 + i) * 128 + c0] = v;
    }
    __syncthreads();
    for (int i = tid; i < 4096; i += 256) sW4[i] = ((const float4*)W2)[i];
    __syncthreads();

    {
        float4 bb = ((const float4*)b2)[tx];
#pragma unroll
        for (int i = 0; i < 8; ++i) { acc[i][0] = bb.x; acc[i][1] = bb.y; acc[i][2] = bb.z; acc[i][3] = bb.w; }
    }
#pragma unroll 2
    for (int k = 0; k < 128; ++k) {
        float4 w = ((const float4*)(sW + k * 128))[tx];
#pragma unroll
        for (int i = 0; i < 8; ++i) {
            float t = sT[(r0 + i) * 128 + k];
            acc[i][0] = fmaf(t, w.x, acc[i][0]);
            acc[i][1] = fmaf(t, w.y, acc[i][1]);
            acc[i][2] = fmaf(t, w.z, acc[i][2]);
            acc[i][3] = fmaf(t, w.w, acc[i][3]);
        }
    }
    // Pool directly from registers
#pragma unroll
    for (int i = 0; i < 8; ++i) {
        int g = sB[r0 + i];
        float* p = pool + (size_t)g * 128 + c0;
        asm volatile("red.global.add.v4.f32 [%0], {%1,%2,%3,%4};"
                     :: "l"(p), "f"(acc[i][0]), "f"(acc[i][1]), "f"(acc[i][2]), "f"(acc[i][3])
                     : "memory");
    }
    if (tx == 0) {
#pragma unroll
        for (int i = 0; i < 8; ++i) atomicAdd(&cnt[sB[r0 + i]], 1.0f);
    }
}

// ---------------------------------------------------------------------------
// Head MLP: z = [pool/cnt, usr]; 140 ->128 ->64 ->32 ->16 ->1
__global__ __launch_bounds__(128) void head_kernel(
    const float* __restrict__ pool, const float* __restrict__ cnt,
    const float* __restrict__ usr,
    const float* __restrict__ w1, const float* __restrict__ b1,
    const float* __restrict__ w2, const float* __restrict__ b2,
    const float* __restrict__ w3, const float* __restrict__ b3,
    const float* __restrict__ w4, const float* __restrict__ b4,
    const float* __restrict__ w5, const float* __restrict__ b5,
    float* __restrict__ out)
{
    __shared__ float z[140];
    __shared__ float a1[128];
    __shared__ float a2[64];
    __shared__ float a3[32];
    __shared__ float a4s[16];

    int g = blockIdx.x, t = threadIdx.x;
    float inv = 1.0f / fmaxf(cnt[g], 1.0f);
    z[t] = pool[(size_t)g * 128 + t] * inv;
    if (t < USR) z[128 + t] = usr[(size_t)g * USR + t];
    __syncthreads();

    {
        float s = b1[t];
        for (int k = 0; k < 140; ++k) s = fmaf(z[k], w1[k * 128 + t], s);
        a1[t] = fmaxf(s, 0.f);
    }
    __syncthreads();
    if (t < 64) {
        float s = b2[t];
        for (int k = 0; k < 128; ++k) s = fmaf(a1[k], w2[k * 64 + t], s);
        a2[t] = fmaxf(s, 0.f);
    }
    __syncthreads();
    if (t < 32) {
        float s = b3[t];
        for (int k = 0; k < 64; ++k) s = fmaf(a2[k], w3[k * 32 + t], s);
        a3[t] = fmaxf(s, 0.f);
    }
    __syncthreads();
    if (t < 16) {
        float s = b4[t];
        for (int k = 0; k < 32; ++k) s = fmaf(a3[k], w4[k * 16 + t], s);
        a4s[t] = fmaxf(s, 0.f);
    }
    __syncthreads();
    if (t == 0) {
        float s = b5[0];
        for (int k = 0; k < 16; ++k) s = fmaf(a4s[k], w5[k], s);
        out[g] = s;
    }
}

// ---------------------------------------------------------------------------
extern "C" void kernel_launch(void* const* d_in, const int* in_sizes, int n_in,
                              void* d_out, int out_size)
{
    const float* x     = (const float*)d_in[0];
    const int*   ei    = (const int*)d_in[1];      // int32 (JAX x64 disabled)
    const float* ea    = (const float*)d_in[2];
    const int*   batch = (const int*)d_in[3];      // int32
    const float* usr   = (const float*)d_in[4];
    const float* e1_w = (const float*)d_in[5],  *e1_b = (const float*)d_in[6];
    const float* n1_w1 = (const float*)d_in[7], *n1_b1 = (const float*)d_in[8];
    const float* n1_w2 = (const float*)d_in[9], *n1_b2 = (const float*)d_in[10];
    const float* e2_w = (const float*)d_in[11], *e2_b = (const float*)d_in[12];
    const float* n2_w1 = (const float*)d_in[13], *n2_b1 = (const float*)d_in[14];
    const float* n2_w2 = (const float*)d_in[15], *n2_b2 = (const float*)d_in[16];
    const float* h1_w = (const float*)d_in[17], *h1_b = (const float*)d_in[18];
    const float* h2_w = (const float*)d_in[19], *h2_b = (const float*)d_in[20];
    const float* h3_w = (const float*)d_in[21], *h3_b = (const float*)d_in[22];
    const float* h4_w = (const float*)d_in[23], *h4_b = (const float*)d_in[24];
    const float* h5_w = (const float*)d_in[25], *h5_b = (const float*)d_in[26];
    float* out = (float*)d_out;

    float *agg, *h, *poolbuf;
    cudaGetSymbolAddress((void**)&agg, g_agg);
    cudaGetSymbolAddress((void**)&h, g_h);
    cudaGetSymbolAddress((void**)&poolbuf, g_pool);
    float* pool = poolbuf;
    float* cnt  = poolbuf + (size_t)Gg * 128;

    const int NODE1_SMEM = 12288 * 4;            // 48 KB
    const int NODE2_SMEM = 28672 * 4 + 64 * 4;   // ~112.25 KB + batch ids
    cudaFuncSetAttribute(node1_kernel, cudaFuncAttributeMaxDynamicSharedMemorySize, NODE1_SMEM);
    cudaFuncSetAttribute(node2_kernel, cudaFuncAttributeMaxDynamicSharedMemorySize, NODE2_SMEM);

    int aggN4 = Nn * 64 / 4;                 // 3.2M float4
    int poolN4 = Gg * 129 / 4;

    // layer 1
    zero_kernel<<<(aggN4 + 255) / 256, 256>>>((float4*)agg, aggN4);
    edge_kernel<<<(Ee + 15) / 16, 256>>>(x, ei, ea, e1_w, e1_b, agg);
    node1_kernel<<<Nn / 64, 256, NODE1_SMEM>>>(x, agg, n1_w1, n1_b1, n1_w2, n1_b2, h);

    // layer 2
    zero_kernel<<<(aggN4 + 255) / 256, 256>>>((float4*)agg, aggN4);
    edge_kernel<<<(Ee + 15) / 16, 256>>>(h, ei, ea, e2_w, e2_b, agg);
    zero_kernel<<<(poolN4 + 255) / 256, 256>>>((float4*)poolbuf, poolN4);
    node2_kernel<<<Nn / 64, 256, NODE2_SMEM>>>(h, agg, n2_w1, n2_b1, n2_w2, n2_b2, batch, pool, cnt);

    // head
    head_kernel<<<Gg, 128>>>(pool, cnt, usr,
                             h1_w, h1_b, h2_w, h2_b, h3_w, h3_b, h4_w, h4_b, h5_w, h5_b,
                             out);
}